// round 16
// baseline (speedup 1.0000x reference)
#include <cuda_runtime.h>

#define HWD   96
#define NVOX  (96*96*96)
#define NVOL  8
#define NTOT  (NVOX*NVOL)
#define NELEM (4*NVOX)
#define NWORDS (NTOT/32)        /* 221184 fg-bit words        */

#define TW 8
#define TH 8
#define TROWS (TW*TH)           /* 64 rows per tile           */
#define TVOX (HWD*TW*TH)        /* 6144                       */
#define TILES_W (HWD/TW)        /* 12 */
#define TILES_PER_VOL (TILES_W*TILES_W)   /* 144 */
#define NBLK_LOCAL (NVOL*TILES_PER_VOL)   /* 1152 */
#define NPLANES (TILES_W-1)     /* 11 */
#define QMAX  2560              /* union queue capacity (mean ~2016) */

// scratch (device globals, zero-initialized at load; finalize resets the
// accumulators; all label slots k_boundary can reach are rewritten fresh
// every launch: boundary-row run starts + their tile roots)
__device__ int           g_label[NTOT];
__device__ unsigned int  g_bits[NWORDS];
__device__ double        g_focal;
__device__ int           g_counts[NVOL];
__device__ int           g_done;

// ---------------------------------------------------------------------------
// run start within a 96-bit row mask m[3] for voxel at bit d (pure ALU)
// ---------------------------------------------------------------------------
__device__ __forceinline__ int run_start3(const unsigned int* m, int d)
{
    int j = d >> 5, k = d & 31;
    unsigned int below = (k == 0) ? 0u : ((1u << k) - 1u);
    unsigned int x = ~m[j] & below;
    if (x) return (j << 5) + (32 - __clz(x));
    while (--j >= 0) {
        x = ~m[j];
        if (x) return (j << 5) + (32 - __clz(x));
    }
    return 0;
}

// ---------------------------------------------------------------------------
// focal + fg bits, 8 elements/thread (2 independent float4 per tensor)
// ---------------------------------------------------------------------------
__global__ void k_init_focal(const float4* __restrict__ pred,
                             const float4* __restrict__ tgt)
{
    int i8 = blockIdx.x * blockDim.x + threadIdx.x;     // NELEM/8 threads
    float4 xa = pred[2*i8], xb = pred[2*i8+1];
    float4 ta = tgt [2*i8], tb = tgt [2*i8+1];
    float xs[8] = {xa.x,xa.y,xa.z,xa.w, xb.x,xb.y,xb.z,xb.w};
    float ts[8] = {ta.x,ta.y,ta.z,ta.w, tb.x,tb.y,tb.z,tb.w};
    unsigned int bytep = 0, bytet = 0;
    float fsum = 0.0f;
    #pragma unroll
    for (int k = 0; k < 8; ++k) {
        float x = xs[k];
        bool  bt = ts[k] > 0.5f;
        bytep |= (x > 0.0f ? 1u : 0u) << k;
        bytet |= (bt       ? 1u : 0u) << k;
        float th;
        asm("tanh.approx.f32 %0, %1;" : "=f"(th) : "f"(0.5f * x));
        float q   = fmaxf(0.5f - 0.5f * th, 1e-12f);   // sigmoid(-x)
        float om  = bt ? q : 1.0f - q;                 // 1 - pt
        float bce = -__logf(q) - (bt ? x : 0.0f);      // softplus(x) - x*t
        float at  = bt ? 0.25f : 0.75f;
        fsum += at * om * om * bce;
    }
    int lane = threadIdx.x & 31;
    unsigned int vp = bytep << (8*(lane & 3));
    unsigned int vt = bytet << (8*(lane & 3));
    #pragma unroll
    for (int off = 1; off <= 2; off <<= 1) {
        vp |= __shfl_xor_sync(0xffffffffu, vp, off);
        vt |= __shfl_xor_sync(0xffffffffu, vt, off);
    }
    if ((lane & 3) == 0) {
        g_bits[i8 >> 2]              = vp;
        g_bits[(i8 >> 2) + NELEM/32] = vt;
    }

    double acc = (double)fsum;
    #pragma unroll
    for (int off = 16; off > 0; off >>= 1)
        acc += __shfl_down_sync(0xffffffffu, acc, off);
    __shared__ double s[8];
    int w = threadIdx.x >> 5;
    if (lane == 0) s[w] = acc;
    __syncthreads();
    if (w == 0) {
        acc = (lane < 8) ? s[lane] : 0.0;
        #pragma unroll
        for (int off = 4; off > 0; off >>= 1)
            acc += __shfl_down_sync(0xffffffffu, acc, off);
        if (lane == 0) atomicAdd(&g_focal, acc);
    }
}

// ---------------------------------------------------------------------------
// shared-memory union-find; unite returns 1 on a successful hook
// ---------------------------------------------------------------------------
__device__ __forceinline__ int rep_s(int* lab, int v)
{
    int curr = lab[v];
    if (curr != v) {
        int next;
        while (curr > (next = lab[curr])) {
            lab[v] = next;
            v = curr;
            curr = next;
        }
    }
    return curr;
}

__device__ __forceinline__ int unite_s(int* lab, int a, int b)
{
    int ra = rep_s(lab, a);
    int rb = rep_s(lab, b);
    while (ra != rb) {
        if (ra > rb) { int t = ra; ra = rb; rb = t; }
        int old = atomicMin(&lab[rb], ra);
        if (old == rb) return 1;       // root -> child transition
        rb = rep_s(lab, old);
    }
    return 0;
}

// ---------------------------------------------------------------------------
// per-tile local CCL over run starts; two-phase union queue with ROOT-PAIR
// WARP DEDUP in Phase B; emit labels for BOUNDARY-ROW starts only
// ---------------------------------------------------------------------------
__global__ __launch_bounds__(256)
void k_local()
{
    __shared__ unsigned int   fgb[TROWS*3];
    __shared__ int            lab[TVOX];
    __shared__ int            growbase[TROWS];
    __shared__ int            snet[8];
    __shared__ unsigned short queue[QMAX];
    __shared__ int            qn;

    int b   = blockIdx.x;
    int vol = b / TILES_PER_VOL;
    int t   = b % TILES_PER_VOL;
    int w0  = (t % TILES_W) * TW;
    int h0  = (t / TILES_W) * TH;
    int tid = threadIdx.x;
    int lane = tid & 31;
    int gbase = vol * NVOX;
    int net = 0;                        // starts - hooks (this thread)

    if (tid == 0) qn = 0;
    if (tid < TROWS)
        growbase[tid] = gbase + (h0 + tid/TW)*HWD*HWD + (w0 + tid%TW)*HWD;
    if (tid < TROWS*3) {
        int row = tid / 3, j = tid % 3;
        int gb  = gbase + (h0 + row/TW)*HWD*HWD + (w0 + row%TW)*HWD;
        fgb[tid] = g_bits[(gb >> 5) + j];
    }
    for (int item = tid; item < TVOX/4; item += 256) {
        int base = item*4;
        ((int4*)lab)[item] = make_int4(base, base+1, base+2, base+3);
    }
    __syncthreads();

    // Phase A: enumerate unions (pure ALU) -> shared ushort queue
    for (int item = tid; item < 112*3; item += 256) {
        int pair = item / 3, j = item % 3;
        int rA, rB;
        if (pair < 56) {                        // +W
            int h = pair / 7, w = pair % 7;
            rA = h*TW + w;  rB = rA + 1;
        } else {                                // +H
            int i = pair - 56;
            rA = i;         rB = i + TW;
        }
        unsigned int mA = fgb[rA*3 + j];
        unsigned int mB = fgb[rB*3 + j];
        unsigned int ov = mA & mB;
        if (!ov) continue;
        unsigned int carry = (j > 0) ?
            ((fgb[rA*3 + j-1] & fgb[rB*3 + j-1]) >> 31) : 0u;
        unsigned int us = ov & ~((ov << 1) | carry);
        int cnt = __popc(us);
        if (!cnt) continue;
        int base = atomicAdd(&qn, cnt);
        while (us) {
            int bit = __ffs(us) - 1;
            us &= us - 1;
            if (base < QMAX) {
                queue[base++] = (unsigned short)((pair << 7) | (j << 5) | bit);
            } else {                            // overflow: process inline
                int d  = 32*j + bit;
                int sA = rA*HWD + run_start3(&fgb[rA*3], d);
                int sB = rB*HWD + run_start3(&fgb[rB*3], d);
                net -= unite_s(lab, sA, sB);
            }
        }
    }
    __syncthreads();

    // Phase B: balanced queue processing with root-pair warp dedup
    {
        int qcount = qn < QMAX ? qn : QMAX;
        int qpad   = (qcount + 255) & ~255;     // warp-uniform trip count
        for (int i = tid; i < qpad; i += 256) {
            bool valid = (i < qcount);
            int ra = 0, rb = 0;
            unsigned int key = 0xFFFFFFFFu;
            if (valid) {
                int e = queue[i];
                int pair = e >> 7, j = (e >> 5) & 3, bit = e & 31;
                int rA, rB;
                if (pair < 56) {
                    int h = pair / 7, w = pair % 7;
                    rA = h*TW + w;  rB = rA + 1;
                } else {
                    int i2 = pair - 56;
                    rA = i2;        rB = i2 + TW;
                }
                int d  = 32*j + bit;
                ra = rep_s(lab, rA*HWD + run_start3(&fgb[rA*3], d));
                rb = rep_s(lab, rB*HWD + run_start3(&fgb[rB*3], d));
                if (ra > rb) { int tt = ra; ra = rb; rb = tt; }
                if (ra != rb) key = ((unsigned)ra << 13) | (unsigned)rb;
                else          valid = false;    // already same component
            }
            unsigned grp = __match_any_sync(0xffffffffu, key);
            if (valid && lane == (__ffs(grp) - 1))
                net -= unite_s(lab, ra, rb);
        }
    }
    __syncthreads();

    // emit: count ALL run starts; chase+write g_label only for boundary-row
    // starts (w in {0,7} or h in {0,7}) and self-label their roots
    for (int item = tid; item < TROWS*3; item += 256) {
        int row = item / 3, j = item % 3;
        unsigned int m = fgb[item];
        if (!m) continue;
        unsigned int carry = (j > 0) ? (fgb[item-1] >> 31) : 0u;
        unsigned int st = m & ~((m << 1) | (carry & 1u));
        if (!st) continue;
        net += __popc(st);
        int w = row & 7, h = row >> 3;
        if (w != 0 && w != TW-1 && h != 0 && h != TH-1) continue;
        int gb = growbase[row];
        while (st) {
            int bit = __ffs(st) - 1;
            st &= st - 1;
            int s = row*HWD + 32*j + bit;
            int r = lab[s];
            while (r != lab[r]) r = lab[r];
            int gr = growbase[r / HWD] + (r % HWD);
            g_label[gb + 32*j + bit] = gr;
            g_label[gr] = gr;
        }
    }

    // block reduce net -> single atomic per block
    #pragma unroll
    for (int off = 16; off > 0; off >>= 1)
        net += __shfl_down_sync(0xffffffffu, net, off);
    int wrp = tid >> 5;
    if (lane == 0) snet[wrp] = net;
    __syncthreads();
    if (tid == 0) {
        int tot = 0;
        #pragma unroll
        for (int k = 0; k < 8; ++k) tot += snet[k];
        if (tot) atomicAdd(&g_counts[vol], tot);
    }
}

// ---------------------------------------------------------------------------
// global union-find (boundary links, 4-bit chunks) with WARP DEDUP on the
// depth-1 label pair; hooks subtracted; LAST block finalizes + resets state
// ---------------------------------------------------------------------------
__device__ __forceinline__ int rep_g(int v)
{
    int curr = g_label[v];
    if (curr != v) {
        int next;
        while (curr > (next = g_label[curr])) {
            g_label[v] = next;
            v = curr;
            curr = next;
        }
    }
    return curr;
}

__device__ __forceinline__ int unite_g(int a, int b)
{
    int ra = rep_g(a);
    int rb = rep_g(b);
    while (ra != rb) {
        if (ra > rb) { int t = ra; ra = rb; rb = t; }
        int old = atomicMin(&g_label[rb], ra);
        if (old == rb) return 1;
        rb = rep_g(old);
    }
    return 0;
}

#define ROWS_PER_AXIS (NVOL * NPLANES * HWD)   /* 8448 row pairs per axis */
#define BITEMS (2 * ROWS_PER_AXIS * 24)        /* 405504 = 1584 * 256     */

__global__ void k_boundary(float* __restrict__ out)
{
    int tid  = blockIdx.x * blockDim.x + threadIdx.x;   // always < BITEMS
    int lane = threadIdx.x & 31;
    int part = tid % 24;               // nibble chunk 0..23
    int rp   = tid / 24;
    int j    = part >> 3;              // word 0..2
    int c    = part & 7;               // nibble within word
    int axis = rp / ROWS_PER_AXIS;
    int u    = rp % ROWS_PER_AXIS;
    int vol  = u / (NPLANES * HWD);
    int r2   = u % (NPLANES * HWD);
    int p    = r2 / HWD;
    int q    = r2 % HWD;
    int offA, offB;
    if (axis == 0) {                   // w = 8p+7 -> w+1
        offA = vol*NVOX + q*HWD*HWD + (TW*p + TW-1)*HWD;
        offB = offA + HWD;
    } else {                           // h = 8p+7 -> h+1
        offA = vol*NVOX + (TH*p + TH-1)*HWD*HWD + q*HWD;
        offB = offA + HWD*HWD;
    }
    unsigned int wA[3] = {0,0,0}, wB[3] = {0,0,0};
    unsigned int us = 0;
    {
        unsigned int a  = g_bits[(offA >> 5) + j];
        unsigned int bm = g_bits[(offB >> 5) + j];
        unsigned int ov = a & bm;
        if (ov) {
            #pragma unroll
            for (int k = 0; k < 3; ++k) {
                wA[k] = g_bits[(offA >> 5) + k];
                wB[k] = g_bits[(offB >> 5) + k];
            }
            unsigned int carry = (j > 0) ? ((wA[j-1] & wB[j-1]) >> 31) : 0u;
            us = ov & ~((ov << 1) | carry);
            us &= 0xFu << (4*c);
        }
    }
    int cnt    = __popc(us);
    int maxcnt = __reduce_max_sync(0xffffffffu, (unsigned)cnt);
    int hooks  = 0;
    for (int k = 0; k < maxcnt; ++k) {
        bool valid = (k < cnt);
        unsigned long long pairv = ~0ull;
        int lA = 0, lB = 0;
        if (valid) {
            int bit = __ffs(us) - 1;
            us &= us - 1;
            int d  = 32*j + bit;
            int sA = offA + run_start3(wA, d);
            int sB = offB + run_start3(wB, d);
            lA = g_label[sA];          // depth-1: tile root (or ancestor)
            lB = g_label[sB];
            pairv = ((unsigned long long)(unsigned)lA << 32) | (unsigned)lB;
        }
        unsigned grp = __match_any_sync(0xffffffffu, pairv);
        if (valid && lane == (__ffs(grp) - 1))
            hooks += unite_g(lA, lB);  // leader per distinct label pair
    }
    // warp aggregate (vol is warp-uniform: 25344 items/vol, 32 | 25344)
    #pragma unroll
    for (int off = 16; off > 0; off >>= 1)
        hooks += __shfl_down_sync(0xffffffffu, hooks, off);
    if (lane == 0 && hooks)
        atomicAdd(&g_counts[vol], -hooks);

    // ---- last-block finalize ----
    __shared__ bool isLast;
    __syncthreads();
    if (threadIdx.x == 0) {
        __threadfence();
        isLast = (atomicAdd(&g_done, 1) == (int)gridDim.x - 1);
    }
    __syncthreads();
    if (isLast && threadIdx.x == 0) {
        double focal = g_focal / (double)NELEM;
        float c0 = (float)g_counts[0], c1 = (float)g_counts[1];
        float c2 = (float)g_counts[2], c3 = (float)g_counts[3];
        float t0 = (float)g_counts[4], t1 = (float)g_counts[5];
        float t2 = (float)g_counts[6], t3 = (float)g_counts[7];
        float ccp0 = 0.5f*(c0 + c2), ccp1 = 0.5f*(c1 + c3);
        float cct0 = 0.5f*(t0 + t2), cct1 = 0.5f*(t1 + t3);
        float topo = 0.5f*(fabsf(ccp0 - cct0) + fabsf(ccp1 - cct1));
        out[0] = (float)focal + 0.1f * topo;
        // reset accumulators so the next graph replay starts clean
        g_focal = 0.0;
        #pragma unroll
        for (int k = 0; k < NVOL; ++k) g_counts[k] = 0;
        g_done = 0;
    }
}

// ---------------------------------------------------------------------------
extern "C" void kernel_launch(void* const* d_in, const int* in_sizes, int n_in,
                              void* d_out, int out_size)
{
    const float4* pred = (const float4*)d_in[0];
    const float4* tgt  = (const float4*)d_in[1];
    float*        out  = (float*)d_out;

    const int T = 256;
    k_init_focal<<<NELEM/8/T, T>>>(pred, tgt);
    k_local     <<<NBLK_LOCAL, T>>>();
    k_boundary  <<<BITEMS/T, T>>>(out);
}

// round 17
// speedup vs baseline: 1.0704x; 1.0704x over previous
#include <cuda_runtime.h>

#define HWD   96
#define NVOX  (96*96*96)
#define NVOL  8
#define NTOT  (NVOX*NVOL)
#define NELEM (4*NVOX)
#define NWORDS (NTOT/32)        /* 221184 fg-bit words        */

#define TW 8
#define TH 8
#define TROWS (TW*TH)           /* 64 rows per tile           */
#define TVOX (HWD*TW*TH)        /* 6144                       */
#define TILES_W (HWD/TW)        /* 12 */
#define TILES_PER_VOL (TILES_W*TILES_W)   /* 144 */
#define NBLK_LOCAL (NVOL*TILES_PER_VOL)   /* 1152 */
#define NPLANES (TILES_W-1)     /* 11 */
#define QMAX  2560              /* union queue capacity (mean ~2016) */

// scratch (device globals, zero-initialized at load; finalize resets the
// accumulators; all label slots k_boundary can reach are rewritten fresh
// every launch: boundary-row run starts + their tile roots)
__device__ int           g_label[NTOT];
__device__ unsigned int  g_bits[NWORDS];
__device__ double        g_focal;
__device__ int           g_counts[NVOL];
__device__ int           g_done;

// ---------------------------------------------------------------------------
// run start within a 96-bit row mask m[3] for voxel at bit d (pure ALU)
// ---------------------------------------------------------------------------
__device__ __forceinline__ int run_start3(const unsigned int* m, int d)
{
    int j = d >> 5, k = d & 31;
    unsigned int below = (k == 0) ? 0u : ((1u << k) - 1u);
    unsigned int x = ~m[j] & below;
    if (x) return (j << 5) + (32 - __clz(x));
    while (--j >= 0) {
        x = ~m[j];
        if (x) return (j << 5) + (32 - __clz(x));
    }
    return 0;
}

// ---------------------------------------------------------------------------
// focal + fg bits, 16 elements/thread (4 independent float4 per tensor)
// ---------------------------------------------------------------------------
__global__ void k_init_focal(const float4* __restrict__ pred,
                             const float4* __restrict__ tgt)
{
    int i16 = blockIdx.x * blockDim.x + threadIdx.x;    // NELEM/16 threads
    float4 x4[4], t4[4];
    #pragma unroll
    for (int q = 0; q < 4; ++q) {
        x4[q] = pred[4*i16 + q];
        t4[q] = tgt [4*i16 + q];
    }
    unsigned int hwp = 0, hwt = 0;                      // 16 bits each
    float fsum = 0.0f;
    #pragma unroll
    for (int q = 0; q < 4; ++q) {
        const float* xs = &x4[q].x;
        const float* ts = &t4[q].x;
        #pragma unroll
        for (int k = 0; k < 4; ++k) {
            float x = xs[k];
            bool  bt = ts[k] > 0.5f;
            int   kk = 4*q + k;
            hwp |= (x > 0.0f ? 1u : 0u) << kk;
            hwt |= (bt       ? 1u : 0u) << kk;
            float th;
            asm("tanh.approx.f32 %0, %1;" : "=f"(th) : "f"(0.5f * x));
            float qq  = fmaxf(0.5f - 0.5f * th, 1e-12f);   // sigmoid(-x)
            float om  = bt ? qq : 1.0f - qq;               // 1 - pt
            float bce = -__logf(qq) - (bt ? x : 0.0f);     // softplus(x)-x*t
            float at  = bt ? 0.25f : 0.75f;
            fsum += at * om * om * bce;
        }
    }
    int lane = threadIdx.x & 31;
    unsigned int vp = hwp << (16*(lane & 1));
    unsigned int vt = hwt << (16*(lane & 1));
    vp |= __shfl_xor_sync(0xffffffffu, vp, 1);
    vt |= __shfl_xor_sync(0xffffffffu, vt, 1);
    if ((lane & 1) == 0) {
        g_bits[i16 >> 1]              = vp;
        g_bits[(i16 >> 1) + NELEM/32] = vt;
    }

    double acc = (double)fsum;
    #pragma unroll
    for (int off = 16; off > 0; off >>= 1)
        acc += __shfl_down_sync(0xffffffffu, acc, off);
    __shared__ double s[8];
    int w = threadIdx.x >> 5;
    if (lane == 0) s[w] = acc;
    __syncthreads();
    if (w == 0) {
        acc = (lane < 8) ? s[lane] : 0.0;
        #pragma unroll
        for (int off = 4; off > 0; off >>= 1)
            acc += __shfl_down_sync(0xffffffffu, acc, off);
        if (lane == 0) atomicAdd(&g_focal, acc);
    }
}

// ---------------------------------------------------------------------------
// shared-memory union-find; unite returns 1 on a successful hook
// ---------------------------------------------------------------------------
__device__ __forceinline__ int rep_s(int* lab, int v)
{
    int curr = lab[v];
    if (curr != v) {
        int next;
        while (curr > (next = lab[curr])) {
            lab[v] = next;
            v = curr;
            curr = next;
        }
    }
    return curr;
}

__device__ __forceinline__ int unite_s(int* lab, int a, int b)
{
    int ra = rep_s(lab, a);
    int rb = rep_s(lab, b);
    while (ra != rb) {
        if (ra > rb) { int t = ra; ra = rb; rb = t; }
        int old = atomicMin(&lab[rb], ra);
        if (old == rb) return 1;       // root -> child transition
        rb = rep_s(lab, old);
    }
    return 0;
}

// ---------------------------------------------------------------------------
// per-tile local CCL over run starts; two-phase union queue (ushort-encoded,
// plain balanced Phase B -- R15 proven); emit BOUNDARY-ROW labels only
// ---------------------------------------------------------------------------
__global__ __launch_bounds__(256)
void k_local()
{
    __shared__ unsigned int   fgb[TROWS*3];
    __shared__ int            lab[TVOX];
    __shared__ int            growbase[TROWS];
    __shared__ int            snet[8];
    __shared__ unsigned short queue[QMAX];
    __shared__ int            qn;

    int b   = blockIdx.x;
    int vol = b / TILES_PER_VOL;
    int t   = b % TILES_PER_VOL;
    int w0  = (t % TILES_W) * TW;
    int h0  = (t / TILES_W) * TH;
    int tid = threadIdx.x;
    int gbase = vol * NVOX;
    int net = 0;                        // starts - hooks (this thread)

    if (tid == 0) qn = 0;
    if (tid < TROWS)
        growbase[tid] = gbase + (h0 + tid/TW)*HWD*HWD + (w0 + tid%TW)*HWD;
    if (tid < TROWS*3) {
        int row = tid / 3, j = tid % 3;
        int gb  = gbase + (h0 + row/TW)*HWD*HWD + (w0 + row%TW)*HWD;
        fgb[tid] = g_bits[(gb >> 5) + j];
    }
    for (int item = tid; item < TVOX/4; item += 256) {
        int base = item*4;
        ((int4*)lab)[item] = make_int4(base, base+1, base+2, base+3);
    }
    __syncthreads();

    // Phase A: enumerate unions (pure ALU) -> shared ushort queue
    for (int item = tid; item < 112*3; item += 256) {
        int pair = item / 3, j = item % 3;
        int rA, rB;
        if (pair < 56) {                        // +W
            int h = pair / 7, w = pair % 7;
            rA = h*TW + w;  rB = rA + 1;
        } else {                                // +H
            int i = pair - 56;
            rA = i;         rB = i + TW;
        }
        unsigned int mA = fgb[rA*3 + j];
        unsigned int mB = fgb[rB*3 + j];
        unsigned int ov = mA & mB;
        if (!ov) continue;
        unsigned int carry = (j > 0) ?
            ((fgb[rA*3 + j-1] & fgb[rB*3 + j-1]) >> 31) : 0u;
        unsigned int us = ov & ~((ov << 1) | carry);
        int cnt = __popc(us);
        if (!cnt) continue;
        int base = atomicAdd(&qn, cnt);
        while (us) {
            int bit = __ffs(us) - 1;
            us &= us - 1;
            if (base < QMAX) {
                queue[base++] = (unsigned short)((pair << 7) | (j << 5) | bit);
            } else {                            // overflow: process inline
                int d  = 32*j + bit;
                int sA = rA*HWD + run_start3(&fgb[rA*3], d);
                int sB = rB*HWD + run_start3(&fgb[rB*3], d);
                net -= unite_s(lab, sA, sB);
            }
        }
    }
    __syncthreads();

    // Phase B: process queue uniformly (~8 unions/thread, balanced)
    {
        int qcount = qn < QMAX ? qn : QMAX;
        for (int i = tid; i < qcount; i += 256) {
            int e = queue[i];
            int pair = e >> 7, j = (e >> 5) & 3, bit = e & 31;
            int rA, rB;
            if (pair < 56) {
                int h = pair / 7, w = pair % 7;
                rA = h*TW + w;  rB = rA + 1;
            } else {
                int i2 = pair - 56;
                rA = i2;        rB = i2 + TW;
            }
            int d  = 32*j + bit;
            int sA = rA*HWD + run_start3(&fgb[rA*3], d);
            int sB = rB*HWD + run_start3(&fgb[rB*3], d);
            net -= unite_s(lab, sA, sB);
        }
    }
    __syncthreads();

    // emit: count ALL run starts; chase+write g_label only for boundary-row
    // starts (w in {0,7} or h in {0,7}) and self-label their roots
    for (int item = tid; item < TROWS*3; item += 256) {
        int row = item / 3, j = item % 3;
        unsigned int m = fgb[item];
        if (!m) continue;
        unsigned int carry = (j > 0) ? (fgb[item-1] >> 31) : 0u;
        unsigned int st = m & ~((m << 1) | (carry & 1u));
        if (!st) continue;
        net += __popc(st);
        int w = row & 7, h = row >> 3;
        if (w != 0 && w != TW-1 && h != 0 && h != TH-1) continue;
        int gb = growbase[row];
        while (st) {
            int bit = __ffs(st) - 1;
            st &= st - 1;
            int s = row*HWD + 32*j + bit;
            int r = lab[s];
            while (r != lab[r]) r = lab[r];
            int gr = growbase[r / HWD] + (r % HWD);
            g_label[gb + 32*j + bit] = gr;
            g_label[gr] = gr;
        }
    }

    // block reduce net -> single atomic per block
    #pragma unroll
    for (int off = 16; off > 0; off >>= 1)
        net += __shfl_down_sync(0xffffffffu, net, off);
    int lane = tid & 31, wrp = tid >> 5;
    if (lane == 0) snet[wrp] = net;
    __syncthreads();
    if (tid == 0) {
        int tot = 0;
        #pragma unroll
        for (int k = 0; k < 8; ++k) tot += snet[k];
        if (tot) atomicAdd(&g_counts[vol], tot);
    }
}

// ---------------------------------------------------------------------------
// global union-find (boundary links, 4-bit chunks) with WARP DEDUP on the
// depth-1 label pair; hooks subtracted; LAST block finalizes + resets state
// ---------------------------------------------------------------------------
__device__ __forceinline__ int rep_g(int v)
{
    int curr = g_label[v];
    if (curr != v) {
        int next;
        while (curr > (next = g_label[curr])) {
            g_label[v] = next;
            v = curr;
            curr = next;
        }
    }
    return curr;
}

__device__ __forceinline__ int unite_g(int a, int b)
{
    int ra = rep_g(a);
    int rb = rep_g(b);
    while (ra != rb) {
        if (ra > rb) { int t = ra; ra = rb; rb = t; }
        int old = atomicMin(&g_label[rb], ra);
        if (old == rb) return 1;
        rb = rep_g(old);
    }
    return 0;
}

#define ROWS_PER_AXIS (NVOL * NPLANES * HWD)   /* 8448 row pairs per axis */
#define BITEMS (2 * ROWS_PER_AXIS * 24)        /* 405504 = 1584 * 256     */

__global__ void k_boundary(float* __restrict__ out)
{
    int tid  = blockIdx.x * blockDim.x + threadIdx.x;   // always < BITEMS
    int lane = threadIdx.x & 31;
    int part = tid % 24;               // nibble chunk 0..23
    int rp   = tid / 24;
    int j    = part >> 3;              // word 0..2
    int c    = part & 7;               // nibble within word
    int axis = rp / ROWS_PER_AXIS;
    int u    = rp % ROWS_PER_AXIS;
    int vol  = u / (NPLANES * HWD);
    int r2   = u % (NPLANES * HWD);
    int p    = r2 / HWD;
    int q    = r2 % HWD;
    int offA, offB;
    if (axis == 0) {                   // w = 8p+7 -> w+1
        offA = vol*NVOX + q*HWD*HWD + (TW*p + TW-1)*HWD;
        offB = offA + HWD;
    } else {                           // h = 8p+7 -> h+1
        offA = vol*NVOX + (TH*p + TH-1)*HWD*HWD + q*HWD;
        offB = offA + HWD*HWD;
    }
    unsigned int wA[3] = {0,0,0}, wB[3] = {0,0,0};
    unsigned int us = 0;
    {
        unsigned int a  = g_bits[(offA >> 5) + j];
        unsigned int bm = g_bits[(offB >> 5) + j];
        unsigned int ov = a & bm;
        if (ov) {
            #pragma unroll
            for (int k = 0; k < 3; ++k) {
                wA[k] = g_bits[(offA >> 5) + k];
                wB[k] = g_bits[(offB >> 5) + k];
            }
            unsigned int carry = (j > 0) ? ((wA[j-1] & wB[j-1]) >> 31) : 0u;
            us = ov & ~((ov << 1) | carry);
            us &= 0xFu << (4*c);
        }
    }
    int cnt    = __popc(us);
    int maxcnt = __reduce_max_sync(0xffffffffu, (unsigned)cnt);
    int hooks  = 0;
    for (int k = 0; k < maxcnt; ++k) {
        bool valid = (k < cnt);
        unsigned long long pairv = ~0ull;
        int lA = 0, lB = 0;
        if (valid) {
            int bit = __ffs(us) - 1;
            us &= us - 1;
            int d  = 32*j + bit;
            int sA = offA + run_start3(wA, d);
            int sB = offB + run_start3(wB, d);
            lA = g_label[sA];          // depth-1: tile root (or ancestor)
            lB = g_label[sB];
            pairv = ((unsigned long long)(unsigned)lA << 32) | (unsigned)lB;
        }
        unsigned grp = __match_any_sync(0xffffffffu, pairv);
        if (valid && lane == (__ffs(grp) - 1))
            hooks += unite_g(lA, lB);  // leader per distinct label pair
    }
    // warp aggregate (vol is warp-uniform: 25344 items/vol, 32 | 25344)
    #pragma unroll
    for (int off = 16; off > 0; off >>= 1)
        hooks += __shfl_down_sync(0xffffffffu, hooks, off);
    if (lane == 0 && hooks)
        atomicAdd(&g_counts[vol], -hooks);

    // ---- last-block finalize ----
    __shared__ bool isLast;
    __syncthreads();
    if (threadIdx.x == 0) {
        __threadfence();
        isLast = (atomicAdd(&g_done, 1) == (int)gridDim.x - 1);
    }
    __syncthreads();
    if (isLast && threadIdx.x == 0) {
        double focal = g_focal / (double)NELEM;
        float c0 = (float)g_counts[0], c1 = (float)g_counts[1];
        float c2 = (float)g_counts[2], c3 = (float)g_counts[3];
        float t0 = (float)g_counts[4], t1 = (float)g_counts[5];
        float t2 = (float)g_counts[6], t3 = (float)g_counts[7];
        float ccp0 = 0.5f*(c0 + c2), ccp1 = 0.5f*(c1 + c3);
        float cct0 = 0.5f*(t0 + t2), cct1 = 0.5f*(t1 + t3);
        float topo = 0.5f*(fabsf(ccp0 - cct0) + fabsf(ccp1 - cct1));
        out[0] = (float)focal + 0.1f * topo;
        // reset accumulators so the next graph replay starts clean
        g_focal = 0.0;
        #pragma unroll
        for (int k = 0; k < NVOL; ++k) g_counts[k] = 0;
        g_done = 0;
    }
}

// ---------------------------------------------------------------------------
extern "C" void kernel_launch(void* const* d_in, const int* in_sizes, int n_in,
                              void* d_out, int out_size)
{
    const float4* pred = (const float4*)d_in[0];
    const float4* tgt  = (const float4*)d_in[1];
    float*        out  = (float*)d_out;

    const int T = 256;
    k_init_focal<<<NELEM/16/T, T>>>(pred, tgt);
    k_local     <<<NBLK_LOCAL, T>>>();
    k_boundary  <<<BITEMS/T, T>>>(out);
}